// round 5
// baseline (speedup 1.0000x reference)
#include <cuda_runtime.h>
#include <math.h>

#define NN   100000
#define EE   1600000
#define INF_ 256
#define HIDF 64
#define OUTF 40
#define COEF 0.1f   // 2*MU/P

#define SCAN_B 1024
#define NB_SCAN ((NN + SCAN_B - 1) / SCAN_B)   // 98

typedef unsigned long long u64;

// ---- scratch (device globals; zero-initialized at load) ----
__device__ float g_h [NN*HIDF];
__device__ float g_f1[NN*HIDF];
__device__ float g_f2[NN*HIDF];
__device__ float g_dis[NN];
__device__ float g_alpha[NN];
__device__ float g_beta[NN];
__device__ int   g_deg[NN];       // re-zeroed by k_out each launch
__device__ int   g_part[NN];
__device__ int   g_bsum[NB_SCAN];
__device__ int   g_rowp[NN];
__device__ int   g_cur[NN];
__device__ int2  g_csr[EE];       // packed (src, dis[src])

// ---------------------------------------------------------------------------
__device__ __forceinline__ u64 packff(float f) {
    u64 r;
    asm("mov.b64 %0, {%1, %1};" : "=l"(r) : "r"(__float_as_uint(f)));
    return r;
}
__device__ __forceinline__ void ffma2(u64& acc, u64 a, u64 b) {
    asm("fma.rn.f32x2 %0, %1, %2, %0;" : "+l"(acc) : "l"(a), "l"(b));
}
__device__ __forceinline__ float2 unpackff(u64 v) {
    unsigned lo, hi;
    asm("mov.b64 {%0, %1}, %2;" : "=r"(lo), "=r"(hi) : "l"(v));
    return make_float2(__uint_as_float(lo), __uint_as_float(hi));
}

// ---------------------------------------------------------------------------
__global__ void k_degree(const int* __restrict__ dst, int* __restrict__ deg, int E) {
    int e = blockIdx.x * blockDim.x + threadIdx.x;
    if (e < E) atomicAdd(&deg[dst[e]], 1);
}

// scan1 fused with per-node coefficients
__global__ __launch_bounds__(SCAN_B) void k_scan1f(const int* __restrict__ deg,
                                                   int* __restrict__ part,
                                                   int* __restrict__ bsum,
                                                   float* __restrict__ dis,
                                                   float* __restrict__ alpha,
                                                   float* __restrict__ beta) {
    __shared__ int s[SCAN_B];
    int i = blockIdx.x * SCAN_B + threadIdx.x;
    int v = (i < NN) ? deg[i] : 0;

    if (i < NN) {
        float dm = (float)(v > 0 ? v : 1);
        dis[i] = rsqrtf(dm);
        float denom = (v > 0 ? 1.0f : 0.0f) + COEF;
        float a = 1.0f / denom;
        alpha[i] = a;
        beta[i]  = COEF * a;
    }

    s[threadIdx.x] = v;
    __syncthreads();
#pragma unroll
    for (int off = 1; off < SCAN_B; off <<= 1) {
        int t = (threadIdx.x >= off) ? s[threadIdx.x - off] : 0;
        __syncthreads();
        s[threadIdx.x] += t;
        __syncthreads();
    }
    if (i < NN) part[i] = s[threadIdx.x] - v;
    if (threadIdx.x == SCAN_B - 1) bsum[blockIdx.x] = s[SCAN_B - 1];
}

__global__ __launch_bounds__(128) void k_scan2(int* __restrict__ bsum, int nb) {
    __shared__ int s[128];
    int v = (threadIdx.x < nb) ? bsum[threadIdx.x] : 0;
    s[threadIdx.x] = v;
    __syncthreads();
#pragma unroll
    for (int off = 1; off < 128; off <<= 1) {
        int t = (threadIdx.x >= off) ? s[threadIdx.x - off] : 0;
        __syncthreads();
        s[threadIdx.x] += t;
        __syncthreads();
    }
    if (threadIdx.x < nb) bsum[threadIdx.x] = s[threadIdx.x] - v;
}

__global__ __launch_bounds__(SCAN_B) void k_scan3(const int* __restrict__ part,
                                                  const int* __restrict__ bsum,
                                                  int* __restrict__ rowp,
                                                  int* __restrict__ cur) {
    int i = blockIdx.x * SCAN_B + threadIdx.x;
    if (i < NN) {
        int r = part[i] + bsum[blockIdx.x];
        rowp[i] = r;
        cur[i]  = r;
    }
}

// ---------------------------------------------------------------------------
__global__ void k_fill(const int* __restrict__ src, const int* __restrict__ dst,
                       const float* __restrict__ dis,
                       int* __restrict__ cur, int2* __restrict__ csr, int E) {
    int e = blockIdx.x * blockDim.x + threadIdx.x;
    if (e >= E) return;
    int s = src[e];
    int d = dst[e];
    int pos = atomicAdd(&cur[d], 1);
    csr[pos] = make_int2(s, __float_as_int(__ldg(&dis[s])));
}

// ---------------------------------------------------------------------------
// GEMM1 + ReLU with packed f32x2 FMA (keep this round; profiled next).
__global__ __launch_bounds__(128) void k_gemm1(const float* __restrict__ x,
                                               const float* __restrict__ W1,
                                               const float* __restrict__ b1,
                                               float* __restrict__ h) {
    __shared__ float sx[INF_][34];
    int row0 = blockIdx.x * 32;
    int tid  = threadIdx.x;

    for (int i = tid; i < 32 * (INF_ / 4); i += 128) {
        int r = i >> 6;
        int c = i & 63;
        float4 v = *(const float4*)(x + (size_t)(row0 + r) * INF_ + c * 4);
        sx[c * 4 + 0][r] = v.x;
        sx[c * 4 + 1][r] = v.y;
        sx[c * 4 + 2][r] = v.z;
        sx[c * 4 + 3][r] = v.w;
    }
    __syncthreads();

    int warp = tid >> 5, lane = tid & 31;
    int rbase = warp * 8;

    u64 acc[4][2];
#pragma unroll
    for (int rp = 0; rp < 4; rp++) { acc[rp][0] = 0ull; acc[rp][1] = 0ull; }

#pragma unroll 4
    for (int k = 0; k < INF_; k++) {
        float2 w2 = ((const float2*)(W1 + k * HIDF))[lane];   // cols 2l, 2l+1
        u64 b0 = packff(w2.x);
        u64 b1p = packff(w2.y);
#pragma unroll
        for (int rp = 0; rp < 4; rp++) {
            u64 a = *reinterpret_cast<const u64*>(&sx[k][rbase + rp * 2]);
            ffma2(acc[rp][0], a, b0);
            ffma2(acc[rp][1], a, b1p);
        }
    }

    float2 bv = ((const float2*)b1)[lane];
#pragma unroll
    for (int rp = 0; rp < 4; rp++) {
        float2 c0 = unpackff(acc[rp][0]);
        float2 c1 = unpackff(acc[rp][1]);
        int row = row0 + rbase + rp * 2;
        float2 r0 = make_float2(fmaxf(c0.x + bv.x, 0.f), fmaxf(c1.x + bv.y, 0.f));
        float2 r1 = make_float2(fmaxf(c0.y + bv.x, 0.f), fmaxf(c1.y + bv.y, 0.f));
        ((float2*)(h + (size_t)row * HIDF))[lane]       = r0;
        ((float2*)(h + (size_t)(row + 1) * HIDF))[lane] = r1;
    }
}

// ---------------------------------------------------------------------------
// Gather SpMM v2: warp per node, float4/lane, 2 edges per LDG.128.
// Half-warp 0 (lanes 0-15) handles even-index edges, half-warp 1 odd-index.
// Each half-warp's 16 lanes cover the full 64-float row (float4 each).
__global__ __launch_bounds__(256) void k_spmm_csr(const float* __restrict__ f,
                                                  const float* __restrict__ h,
                                                  const int2* __restrict__ csr,
                                                  const int* __restrict__ rowp,
                                                  const int* __restrict__ deg,
                                                  const float* __restrict__ dis,
                                                  const float* __restrict__ alpha,
                                                  const float* __restrict__ beta,
                                                  float* __restrict__ fout) {
    int node = (blockIdx.x * blockDim.x + threadIdx.x) >> 5;
    if (node >= NN) return;
    int lane = threadIdx.x & 31;
    int half = lane >> 4;
    int l16  = lane & 15;

    int beg = rowp[node];
    int n   = deg[node];

    float4 acc = make_float4(0.f, 0.f, 0.f, 0.f);
    int i = 0;

    // alignment prologue: make (beg + i) even so int4 csr loads are 16B aligned
    if ((beg & 1) && n > 0) {
        int2 e = __ldg(&csr[beg]);                       // broadcast
        float w = (half == 0) ? __int_as_float(e.y) : 0.f;
        float4 v = *(const float4*)(f + (size_t)e.x * HIDF + l16 * 4);
        acc.x = fmaf(w, v.x, acc.x); acc.y = fmaf(w, v.y, acc.y);
        acc.z = fmaf(w, v.z, acc.z); acc.w = fmaf(w, v.w, acc.w);
        i = 1;
    }

    // main loop: 2 edges per iteration, one int4 csr broadcast + one row LDG.128
    for (; i + 2 <= n; i += 2) {
        int4 e2 = __ldg((const int4*)(csr + beg + i));   // 16B aligned, broadcast
        int   s = half ? e2.z : e2.x;
        float w = __int_as_float(half ? e2.w : e2.y);
        float4 v = *(const float4*)(f + (size_t)s * HIDF + l16 * 4);
        acc.x = fmaf(w, v.x, acc.x); acc.y = fmaf(w, v.y, acc.y);
        acc.z = fmaf(w, v.z, acc.z); acc.w = fmaf(w, v.w, acc.w);
    }

    // leftover single edge
    if (i < n) {
        int2 e = __ldg(&csr[beg + i]);
        float w = (half == 0) ? __int_as_float(e.y) : 0.f;
        float4 v = *(const float4*)(f + (size_t)e.x * HIDF + l16 * 4);
        acc.x = fmaf(w, v.x, acc.x); acc.y = fmaf(w, v.y, acc.y);
        acc.z = fmaf(w, v.z, acc.z); acc.w = fmaf(w, v.w, acc.w);
    }

    // cross-half reduce: lanes l and l^16 hold the same columns
    acc.x += __shfl_xor_sync(0xffffffffu, acc.x, 16);
    acc.y += __shfl_xor_sync(0xffffffffu, acc.y, 16);
    acc.z += __shfl_xor_sync(0xffffffffu, acc.z, 16);
    acc.w += __shfl_xor_sync(0xffffffffu, acc.w, 16);

    if (half == 0) {
        float scale = alpha[node] * dis[node];
        float b = beta[node];
        float4 hv = *(const float4*)(h + (size_t)node * HIDF + l16 * 4);
        float4 r;
        r.x = fmaf(scale, acc.x, b * hv.x);
        r.y = fmaf(scale, acc.y, b * hv.y);
        r.z = fmaf(scale, acc.z, b * hv.z);
        r.w = fmaf(scale, acc.w, b * hv.w);
        *(float4*)(fout + (size_t)node * HIDF + l16 * 4) = r;
    }
}

// ---------------------------------------------------------------------------
// GEMM2 + log_softmax, one warp per row. Also re-zeros deg for next launch.
__global__ __launch_bounds__(256) void k_out(const float* __restrict__ f,
                                             const float* __restrict__ W2,
                                             const float* __restrict__ b2,
                                             float* __restrict__ out,
                                             int* __restrict__ deg) {
    int gwarp = (blockIdx.x * blockDim.x + threadIdx.x) >> 5;
    int lane  = threadIdx.x & 31;
    if (gwarp >= NN) return;

    if (lane == 0) deg[gwarp] = 0;

    float2 fr = ((const float2*)(f + (size_t)gwarp * HIDF))[lane];

    float acc0 = b2[lane];
    float acc1 = (lane < 8) ? b2[lane + 32] : -1e30f;

#pragma unroll
    for (int k = 0; k < HIDF; k++) {
        float fv = __shfl_sync(0xffffffffu, (k & 1) ? fr.y : fr.x, k >> 1);
        acc0 = fmaf(fv, W2[k * OUTF + lane], acc0);
        if (lane < 8) acc1 = fmaf(fv, W2[k * OUTF + lane + 32], acc1);
    }

    float m = fmaxf(acc0, acc1);
#pragma unroll
    for (int o = 16; o > 0; o >>= 1) m = fmaxf(m, __shfl_xor_sync(0xffffffffu, m, o));
    float s = expf(acc0 - m) + ((lane < 8) ? expf(acc1 - m) : 0.f);
#pragma unroll
    for (int o = 16; o > 0; o >>= 1) s += __shfl_xor_sync(0xffffffffu, s, o);
    float ls = m + logf(s);

    out[(size_t)gwarp * OUTF + lane] = acc0 - ls;
    if (lane < 8) out[(size_t)gwarp * OUTF + lane + 32] = acc1 - ls;
}

// ---------------------------------------------------------------------------
extern "C" void kernel_launch(void* const* d_in, const int* in_sizes, int n_in,
                              void* d_out, int out_size) {
    const float* x   = (const float*)d_in[0];
    const int*   ei  = (const int*)  d_in[1];
    const float* W1  = (const float*)d_in[2];
    const float* b1  = (const float*)d_in[3];
    const float* W2  = (const float*)d_in[4];
    const float* b2  = (const float*)d_in[5];
    float* out = (float*)d_out;

    const int E = in_sizes[1] / 2;
    const int* src = ei;
    const int* dst = ei + E;

    float *h, *f1, *f2, *dis, *alpha, *beta;
    int *deg, *part, *bsum, *rowp, *cur;
    int2* csr;
    cudaGetSymbolAddress((void**)&h,     g_h);
    cudaGetSymbolAddress((void**)&f1,    g_f1);
    cudaGetSymbolAddress((void**)&f2,    g_f2);
    cudaGetSymbolAddress((void**)&dis,   g_dis);
    cudaGetSymbolAddress((void**)&alpha, g_alpha);
    cudaGetSymbolAddress((void**)&beta,  g_beta);
    cudaGetSymbolAddress((void**)&deg,   g_deg);
    cudaGetSymbolAddress((void**)&part,  g_part);
    cudaGetSymbolAddress((void**)&bsum,  g_bsum);
    cudaGetSymbolAddress((void**)&rowp,  g_rowp);
    cudaGetSymbolAddress((void**)&cur,   g_cur);
    cudaGetSymbolAddress((void**)&csr,   g_csr);

    // one-time stream/event setup
    static cudaStream_t sB = 0;
    static cudaEvent_t evRoot = 0, evB = 0;
    static int use_fork = -1;
    if (use_fork < 0) {
        use_fork = 1;
        if (cudaStreamCreateWithFlags(&sB, cudaStreamNonBlocking) != cudaSuccess) use_fork = 0;
        if (use_fork && cudaEventCreateWithFlags(&evRoot, cudaEventDisableTiming) != cudaSuccess) use_fork = 0;
        if (use_fork && cudaEventCreateWithFlags(&evB, cudaEventDisableTiming) != cudaSuccess) use_fork = 0;
    }
    cudaStream_t sG = 0;
    if (use_fork) {
        cudaEventRecord(evRoot, 0);
        cudaStreamWaitEvent(sB, evRoot, 0);
        sG = sB;
    }

    // prep chain on stream 0; gemm1 submitted 4th (profiler slot) on forked stream
    k_degree <<<(E + 255) / 256, 256>>>(dst, deg, E);                    // submit #1
    k_scan1f <<<NB_SCAN, SCAN_B>>>(deg, part, bsum, dis, alpha, beta);   // submit #2
    k_scan2  <<<1, 128>>>(bsum, NB_SCAN);                                // submit #3
    k_gemm1  <<<NN / 32, 128, 0, sG>>>(x, W1, b1, h);                    // submit #4  <- profiled
    k_scan3  <<<NB_SCAN, SCAN_B>>>(part, bsum, rowp, cur);               // submit #5
    k_fill   <<<(E + 255) / 256, 256>>>(src, dst, dis, cur, csr, E);     // submit #6

    if (use_fork) {
        cudaEventRecord(evB, sB);
        cudaStreamWaitEvent(0, evB, 0);
    }

    k_spmm_csr<<<(NN * 32 + 255) / 256, 256>>>(h,  h, csr, rowp, deg, dis, alpha, beta, f1);
    k_spmm_csr<<<(NN * 32 + 255) / 256, 256>>>(f1, h, csr, rowp, deg, dis, alpha, beta, f2);

    k_out<<<(NN * 32 + 255) / 256, 256>>>(f2, W2, b2, out, deg);
}

// round 6
// speedup vs baseline: 1.0154x; 1.0154x over previous
#include <cuda_runtime.h>
#include <math.h>

#define NN   100000
#define EE   1600000
#define INF_ 256
#define HIDF 64
#define OUTF 40
#define COEF 0.1f   // 2*MU/P

#define SCAN_B 1024
#define NB_SCAN ((NN + SCAN_B - 1) / SCAN_B)   // 98

typedef unsigned long long u64;

// ---- scratch (device globals; zero-initialized at load) ----
__device__ float g_h [NN*HIDF];
__device__ float g_f1[NN*HIDF];
__device__ float g_f2[NN*HIDF];
__device__ float g_dis[NN];
__device__ float g_alpha[NN];
__device__ float g_beta[NN];
__device__ int   g_deg[NN];       // re-zeroed by k_out each launch
__device__ int   g_part[NN];
__device__ int   g_bsum[NB_SCAN];
__device__ int   g_rowp[NN];
__device__ int   g_cur[NN];
__device__ int2  g_csr[EE];       // packed (src, dis[src])

// ---------------------------------------------------------------------------
__device__ __forceinline__ u64 packff(float f) {
    u64 r;
    asm("mov.b64 %0, {%1, %1};" : "=l"(r) : "r"(__float_as_uint(f)));
    return r;
}
__device__ __forceinline__ void ffma2(u64& acc, u64 a, u64 b) {
    asm("fma.rn.f32x2 %0, %1, %2, %0;" : "+l"(acc) : "l"(a), "l"(b));
}
__device__ __forceinline__ float2 unpackff(u64 v) {
    unsigned lo, hi;
    asm("mov.b64 {%0, %1}, %2;" : "=r"(lo), "=r"(hi) : "l"(v));
    return make_float2(__uint_as_float(lo), __uint_as_float(hi));
}

// ---------------------------------------------------------------------------
__global__ void k_degree(const int* __restrict__ dst, int* __restrict__ deg, int E) {
    int e = blockIdx.x * blockDim.x + threadIdx.x;
    if (e < E) atomicAdd(&deg[dst[e]], 1);
}

// scan1 fused with per-node coefficients
__global__ __launch_bounds__(SCAN_B) void k_scan1f(const int* __restrict__ deg,
                                                   int* __restrict__ part,
                                                   int* __restrict__ bsum,
                                                   float* __restrict__ dis,
                                                   float* __restrict__ alpha,
                                                   float* __restrict__ beta) {
    __shared__ int s[SCAN_B];
    int i = blockIdx.x * SCAN_B + threadIdx.x;
    int v = (i < NN) ? deg[i] : 0;

    if (i < NN) {
        float dm = (float)(v > 0 ? v : 1);
        dis[i] = rsqrtf(dm);
        float denom = (v > 0 ? 1.0f : 0.0f) + COEF;
        float a = 1.0f / denom;
        alpha[i] = a;
        beta[i]  = COEF * a;
    }

    s[threadIdx.x] = v;
    __syncthreads();
#pragma unroll
    for (int off = 1; off < SCAN_B; off <<= 1) {
        int t = (threadIdx.x >= off) ? s[threadIdx.x - off] : 0;
        __syncthreads();
        s[threadIdx.x] += t;
        __syncthreads();
    }
    if (i < NN) part[i] = s[threadIdx.x] - v;
    if (threadIdx.x == SCAN_B - 1) bsum[blockIdx.x] = s[SCAN_B - 1];
}

__global__ __launch_bounds__(128) void k_scan2(int* __restrict__ bsum, int nb) {
    __shared__ int s[128];
    int v = (threadIdx.x < nb) ? bsum[threadIdx.x] : 0;
    s[threadIdx.x] = v;
    __syncthreads();
#pragma unroll
    for (int off = 1; off < 128; off <<= 1) {
        int t = (threadIdx.x >= off) ? s[threadIdx.x - off] : 0;
        __syncthreads();
        s[threadIdx.x] += t;
        __syncthreads();
    }
    if (threadIdx.x < nb) bsum[threadIdx.x] = s[threadIdx.x] - v;
}

__global__ __launch_bounds__(SCAN_B) void k_scan3(const int* __restrict__ part,
                                                  const int* __restrict__ bsum,
                                                  int* __restrict__ rowp,
                                                  int* __restrict__ cur) {
    int i = blockIdx.x * SCAN_B + threadIdx.x;
    if (i < NN) {
        int r = part[i] + bsum[blockIdx.x];
        rowp[i] = r;
        cur[i]  = r;
    }
}

// ---------------------------------------------------------------------------
__global__ void k_fill(const int* __restrict__ src, const int* __restrict__ dst,
                       const float* __restrict__ dis,
                       int* __restrict__ cur, int2* __restrict__ csr, int E) {
    int e = blockIdx.x * blockDim.x + threadIdx.x;
    if (e >= E) return;
    int s = src[e];
    int d = dst[e];
    int pos = atomicAdd(&cur[d], 1);
    csr[pos] = make_int2(s, __float_as_int(__ldg(&dis[s])));
}

// ---------------------------------------------------------------------------
// GEMM1 v3 + ReLU, packed f32x2 FMA.
// Block = 128 threads (4 warps), 32 rows x 64 cols.
// smem k-major: sx[k][36] (144B rows, 16B aligned); conflict-free transpose fill
// (lane = row). Main loop: 2 LDS.128 broadcasts (8 rows) + 1 LDG.64 (W1,
// prefetched 1 k ahead) + 8 FFMA2 per k.
__global__ __launch_bounds__(128) void k_gemm1(const float* __restrict__ x,
                                               const float* __restrict__ W1,
                                               const float* __restrict__ b1,
                                               float* __restrict__ h) {
    __shared__ float sx[INF_][36];
    int row0 = blockIdx.x * 32;
    int tid  = threadIdx.x;
    int warp = tid >> 5, lane = tid & 31;

    // transpose fill, conflict-free stores: thread (warp, lane, it) loads
    // x[row0+lane][c4*4..+3] (c4 = warp*16+it) and stores to sx[c4*4+j][lane].
#pragma unroll
    for (int it = 0; it < 16; it++) {
        int c4 = warp * 16 + it;
        float4 v = *(const float4*)(x + (size_t)(row0 + lane) * INF_ + c4 * 4);
        sx[c4 * 4 + 0][lane] = v.x;
        sx[c4 * 4 + 1][lane] = v.y;
        sx[c4 * 4 + 2][lane] = v.z;
        sx[c4 * 4 + 3][lane] = v.w;
    }
    __syncthreads();

    int rbase = warp * 8;

    u64 accA[4], accB[4];
#pragma unroll
    for (int rp = 0; rp < 4; rp++) { accA[rp] = 0ull; accB[rp] = 0ull; }

    float2 wc = ((const float2*)W1)[lane];   // k = 0 prefetch
#pragma unroll 4
    for (int k = 0; k < INF_; k++) {
        float2 wn = (k + 1 < INF_) ? ((const float2*)(W1 + (k + 1) * HIDF))[lane] : wc;
        ulonglong2 A = *(const ulonglong2*)&sx[k][rbase];       // rows +0..3 (2 pairs)
        ulonglong2 B = *(const ulonglong2*)&sx[k][rbase + 4];   // rows +4..7
        u64 b0 = packff(wc.x);
        u64 b1p = packff(wc.y);
        ffma2(accA[0], A.x, b0);  ffma2(accB[0], A.x, b1p);
        ffma2(accA[1], A.y, b0);  ffma2(accB[1], A.y, b1p);
        ffma2(accA[2], B.x, b0);  ffma2(accB[2], B.x, b1p);
        ffma2(accA[3], B.y, b0);  ffma2(accB[3], B.y, b1p);
        wc = wn;
    }

    float2 bv = ((const float2*)b1)[lane];
#pragma unroll
    for (int rp = 0; rp < 4; rp++) {
        float2 c0 = unpackff(accA[rp]);   // (row, row+1) @ col 2l
        float2 c1 = unpackff(accB[rp]);   // (row, row+1) @ col 2l+1
        int row = row0 + rbase + rp * 2;
        float2 r0 = make_float2(fmaxf(c0.x + bv.x, 0.f), fmaxf(c1.x + bv.y, 0.f));
        float2 r1 = make_float2(fmaxf(c0.y + bv.x, 0.f), fmaxf(c1.y + bv.y, 0.f));
        ((float2*)(h + (size_t)row * HIDF))[lane]       = r0;
        ((float2*)(h + (size_t)(row + 1) * HIDF))[lane] = r1;
    }
}

// ---------------------------------------------------------------------------
// Gather SpMM (R3 form): one warp per dst node, float2/lane, 4-deep unroll.
__global__ __launch_bounds__(256) void k_spmm_csr(const float* __restrict__ f,
                                                  const float* __restrict__ h,
                                                  const int2* __restrict__ csr,
                                                  const int* __restrict__ rowp,
                                                  const int* __restrict__ deg,
                                                  const float* __restrict__ dis,
                                                  const float* __restrict__ alpha,
                                                  const float* __restrict__ beta,
                                                  float* __restrict__ fout) {
    int node = (blockIdx.x * blockDim.x + threadIdx.x) >> 5;
    if (node >= NN) return;
    int lane = threadIdx.x & 31;

    int beg = rowp[node];
    int n   = deg[node];

    float ax = 0.f, ay = 0.f;
    int i = 0;
    for (; i + 4 <= n; i += 4) {
        int2 e0 = __ldg(&csr[beg + i]);
        int2 e1 = __ldg(&csr[beg + i + 1]);
        int2 e2 = __ldg(&csr[beg + i + 2]);
        int2 e3 = __ldg(&csr[beg + i + 3]);
        float2 v0 = ((const float2*)(f + (size_t)e0.x * HIDF))[lane];
        float2 v1 = ((const float2*)(f + (size_t)e1.x * HIDF))[lane];
        float2 v2 = ((const float2*)(f + (size_t)e2.x * HIDF))[lane];
        float2 v3 = ((const float2*)(f + (size_t)e3.x * HIDF))[lane];
        float w0 = __int_as_float(e0.y), w1 = __int_as_float(e1.y);
        float w2 = __int_as_float(e2.y), w3 = __int_as_float(e3.y);
        ax = fmaf(w0, v0.x, ax); ay = fmaf(w0, v0.y, ay);
        ax = fmaf(w1, v1.x, ax); ay = fmaf(w1, v1.y, ay);
        ax = fmaf(w2, v2.x, ax); ay = fmaf(w2, v2.y, ay);
        ax = fmaf(w3, v3.x, ax); ay = fmaf(w3, v3.y, ay);
    }
    for (; i < n; i++) {
        int2 e0 = __ldg(&csr[beg + i]);
        float2 v0 = ((const float2*)(f + (size_t)e0.x * HIDF))[lane];
        float w0 = __int_as_float(e0.y);
        ax = fmaf(w0, v0.x, ax); ay = fmaf(w0, v0.y, ay);
    }

    float scale = alpha[node] * dis[node];
    float b = beta[node];
    float2 hv = ((const float2*)(h + (size_t)node * HIDF))[lane];
    float2 r;
    r.x = fmaf(scale, ax, b * hv.x);
    r.y = fmaf(scale, ay, b * hv.y);
    ((float2*)(fout + (size_t)node * HIDF))[lane] = r;
}

// ---------------------------------------------------------------------------
// GEMM2 + log_softmax, one warp per row. Also re-zeros deg for next launch.
__global__ __launch_bounds__(256) void k_out(const float* __restrict__ f,
                                             const float* __restrict__ W2,
                                             const float* __restrict__ b2,
                                             float* __restrict__ out,
                                             int* __restrict__ deg) {
    int gwarp = (blockIdx.x * blockDim.x + threadIdx.x) >> 5;
    int lane  = threadIdx.x & 31;
    if (gwarp >= NN) return;

    if (lane == 0) deg[gwarp] = 0;

    float2 fr = ((const float2*)(f + (size_t)gwarp * HIDF))[lane];

    float acc0 = b2[lane];
    float acc1 = (lane < 8) ? b2[lane + 32] : -1e30f;

#pragma unroll
    for (int k = 0; k < HIDF; k++) {
        float fv = __shfl_sync(0xffffffffu, (k & 1) ? fr.y : fr.x, k >> 1);
        acc0 = fmaf(fv, W2[k * OUTF + lane], acc0);
        if (lane < 8) acc1 = fmaf(fv, W2[k * OUTF + lane + 32], acc1);
    }

    float m = fmaxf(acc0, acc1);
#pragma unroll
    for (int o = 16; o > 0; o >>= 1) m = fmaxf(m, __shfl_xor_sync(0xffffffffu, m, o));
    float s = expf(acc0 - m) + ((lane < 8) ? expf(acc1 - m) : 0.f);
#pragma unroll
    for (int o = 16; o > 0; o >>= 1) s += __shfl_xor_sync(0xffffffffu, s, o);
    float ls = m + logf(s);

    out[(size_t)gwarp * OUTF + lane] = acc0 - ls;
    if (lane < 8) out[(size_t)gwarp * OUTF + lane + 32] = acc1 - ls;
}

// ---------------------------------------------------------------------------
extern "C" void kernel_launch(void* const* d_in, const int* in_sizes, int n_in,
                              void* d_out, int out_size) {
    const float* x   = (const float*)d_in[0];
    const int*   ei  = (const int*)  d_in[1];
    const float* W1  = (const float*)d_in[2];
    const float* b1  = (const float*)d_in[3];
    const float* W2  = (const float*)d_in[4];
    const float* b2  = (const float*)d_in[5];
    float* out = (float*)d_out;

    const int E = in_sizes[1] / 2;
    const int* src = ei;
    const int* dst = ei + E;

    float *h, *f1, *f2, *dis, *alpha, *beta;
    int *deg, *part, *bsum, *rowp, *cur;
    int2* csr;
    cudaGetSymbolAddress((void**)&h,     g_h);
    cudaGetSymbolAddress((void**)&f1,    g_f1);
    cudaGetSymbolAddress((void**)&f2,    g_f2);
    cudaGetSymbolAddress((void**)&dis,   g_dis);
    cudaGetSymbolAddress((void**)&alpha, g_alpha);
    cudaGetSymbolAddress((void**)&beta,  g_beta);
    cudaGetSymbolAddress((void**)&deg,   g_deg);
    cudaGetSymbolAddress((void**)&part,  g_part);
    cudaGetSymbolAddress((void**)&bsum,  g_bsum);
    cudaGetSymbolAddress((void**)&rowp,  g_rowp);
    cudaGetSymbolAddress((void**)&cur,   g_cur);
    cudaGetSymbolAddress((void**)&csr,   g_csr);

    // one-time stream/event setup
    static cudaStream_t sB = 0;
    static cudaEvent_t evRoot = 0, evB = 0;
    static int use_fork = -1;
    if (use_fork < 0) {
        use_fork = 1;
        if (cudaStreamCreateWithFlags(&sB, cudaStreamNonBlocking) != cudaSuccess) use_fork = 0;
        if (use_fork && cudaEventCreateWithFlags(&evRoot, cudaEventDisableTiming) != cudaSuccess) use_fork = 0;
        if (use_fork && cudaEventCreateWithFlags(&evB, cudaEventDisableTiming) != cudaSuccess) use_fork = 0;
    }
    cudaStream_t sG = 0;
    if (use_fork) {
        cudaEventRecord(evRoot, 0);
        cudaStreamWaitEvent(sB, evRoot, 0);
        sG = sB;
    }

    // prep chain on stream 0; gemm1 submitted 4th (profiler slot) on forked stream
    k_degree <<<(E + 255) / 256, 256>>>(dst, deg, E);                    // submit #1
    k_scan1f <<<NB_SCAN, SCAN_B>>>(deg, part, bsum, dis, alpha, beta);   // submit #2
    k_scan2  <<<1, 128>>>(bsum, NB_SCAN);                                // submit #3
    k_gemm1  <<<NN / 32, 128, 0, sG>>>(x, W1, b1, h);                    // submit #4  <- profiled
    k_scan3  <<<NB_SCAN, SCAN_B>>>(part, bsum, rowp, cur);               // submit #5
    k_fill   <<<(E + 255) / 256, 256>>>(src, dst, dis, cur, csr, E);     // submit #6

    if (use_fork) {
        cudaEventRecord(evB, sB);
        cudaStreamWaitEvent(0, evB, 0);
    }

    k_spmm_csr<<<(NN * 32 + 255) / 256, 256>>>(h,  h, csr, rowp, deg, dis, alpha, beta, f1);
    k_spmm_csr<<<(NN * 32 + 255) / 256, 256>>>(f1, h, csr, rowp, deg, dis, alpha, beta, f2);

    k_out<<<(NN * 32 + 255) / 256, 256>>>(f2, W2, b2, out, deg);
}

// round 7
// speedup vs baseline: 1.0430x; 1.0272x over previous
#include <cuda_runtime.h>
#include <math.h>

#define NN   100000
#define EE   1600000
#define INF_ 256
#define HIDF 64
#define OUTF 40
#define COEF 0.1f   // 2*MU/P

#define SCAN_B 1024
#define NB_SCAN ((NN + SCAN_B - 1) / SCAN_B)   // 98

typedef unsigned long long u64;

// ---- scratch (device globals; zero-initialized at load) ----
__device__ float g_h [NN*HIDF];
__device__ float g_f1[NN*HIDF];
__device__ float g_f2[NN*HIDF];
__device__ float g_dis[NN];
__device__ float g_alpha[NN];
__device__ float g_beta[NN];
__device__ int   g_deg[NN];       // re-zeroed by k_out each launch
__device__ int   g_part[NN];
__device__ int   g_bsum[NB_SCAN];
__device__ int   g_rowp[NN];
__device__ int   g_cur[NN];
__device__ int2  g_csr[EE];       // packed (src, dis[src])

// ---------------------------------------------------------------------------
__device__ __forceinline__ u64 packff(float f) {
    u64 r;
    asm("mov.b64 %0, {%1, %1};" : "=l"(r) : "r"(__float_as_uint(f)));
    return r;
}
__device__ __forceinline__ void ffma2(u64& acc, u64 a, u64 b) {
    asm("fma.rn.f32x2 %0, %1, %2, %0;" : "+l"(acc) : "l"(a), "l"(b));
}
__device__ __forceinline__ float2 unpackff(u64 v) {
    unsigned lo, hi;
    asm("mov.b64 {%0, %1}, %2;" : "=r"(lo), "=r"(hi) : "l"(v));
    return make_float2(__uint_as_float(lo), __uint_as_float(hi));
}

// ---------------------------------------------------------------------------
__global__ void k_degree(const int* __restrict__ dst, int* __restrict__ deg, int E) {
    int e = blockIdx.x * blockDim.x + threadIdx.x;
    if (e < E) atomicAdd(&deg[dst[e]], 1);
}

// scan1 fused with per-node coefficients
__global__ __launch_bounds__(SCAN_B) void k_scan1f(const int* __restrict__ deg,
                                                   int* __restrict__ part,
                                                   int* __restrict__ bsum,
                                                   float* __restrict__ dis,
                                                   float* __restrict__ alpha,
                                                   float* __restrict__ beta) {
    __shared__ int s[SCAN_B];
    int i = blockIdx.x * SCAN_B + threadIdx.x;
    int v = (i < NN) ? deg[i] : 0;

    if (i < NN) {
        float dm = (float)(v > 0 ? v : 1);
        dis[i] = rsqrtf(dm);
        float denom = (v > 0 ? 1.0f : 0.0f) + COEF;
        float a = 1.0f / denom;
        alpha[i] = a;
        beta[i]  = COEF * a;
    }

    s[threadIdx.x] = v;
    __syncthreads();
#pragma unroll
    for (int off = 1; off < SCAN_B; off <<= 1) {
        int t = (threadIdx.x >= off) ? s[threadIdx.x - off] : 0;
        __syncthreads();
        s[threadIdx.x] += t;
        __syncthreads();
    }
    if (i < NN) part[i] = s[threadIdx.x] - v;
    if (threadIdx.x == SCAN_B - 1) bsum[blockIdx.x] = s[SCAN_B - 1];
}

// fused scan2+scan3: each block locally reduces bsum[0..blockIdx.x) then
// finalizes rowp/cur. (98 values; redundant per-block work is trivial.)
__global__ __launch_bounds__(SCAN_B) void k_scan23(const int* __restrict__ part,
                                                   const int* __restrict__ bsum,
                                                   int* __restrict__ rowp,
                                                   int* __restrict__ cur) {
    __shared__ int sb[128];
    if (threadIdx.x < 128)
        sb[threadIdx.x] = (threadIdx.x < blockIdx.x && threadIdx.x < NB_SCAN)
                          ? bsum[threadIdx.x] : 0;
    __syncthreads();
#pragma unroll
    for (int off = 64; off >= 1; off >>= 1) {
        if (threadIdx.x < off) sb[threadIdx.x] += sb[threadIdx.x + off];
        __syncthreads();
    }
    int base = sb[0];
    int i = blockIdx.x * SCAN_B + threadIdx.x;
    if (i < NN) {
        int r = part[i] + base;
        rowp[i] = r;
        cur[i]  = r;
    }
}

// ---------------------------------------------------------------------------
__global__ void k_fill(const int* __restrict__ src, const int* __restrict__ dst,
                       const float* __restrict__ dis,
                       int* __restrict__ cur, int2* __restrict__ csr, int E) {
    int e = blockIdx.x * blockDim.x + threadIdx.x;
    if (e >= E) return;
    int s = src[e];
    int d = dst[e];
    int pos = atomicAdd(&cur[d], 1);
    csr[pos] = make_int2(s, __float_as_int(__ldg(&dis[s])));
}

// ---------------------------------------------------------------------------
// GEMM1 + ReLU, packed f32x2 FMA (R3 "v2" version — best measured: 114us).
__global__ __launch_bounds__(128) void k_gemm1(const float* __restrict__ x,
                                               const float* __restrict__ W1,
                                               const float* __restrict__ b1,
                                               float* __restrict__ h) {
    __shared__ float sx[INF_][34];
    int row0 = blockIdx.x * 32;
    int tid  = threadIdx.x;

    for (int i = tid; i < 32 * (INF_ / 4); i += 128) {
        int r = i >> 6;
        int c = i & 63;
        float4 v = *(const float4*)(x + (size_t)(row0 + r) * INF_ + c * 4);
        sx[c * 4 + 0][r] = v.x;
        sx[c * 4 + 1][r] = v.y;
        sx[c * 4 + 2][r] = v.z;
        sx[c * 4 + 3][r] = v.w;
    }
    __syncthreads();

    int warp = tid >> 5, lane = tid & 31;
    int rbase = warp * 8;

    u64 acc[4][2];
#pragma unroll
    for (int rp = 0; rp < 4; rp++) { acc[rp][0] = 0ull; acc[rp][1] = 0ull; }

#pragma unroll 4
    for (int k = 0; k < INF_; k++) {
        float2 w2 = ((const float2*)(W1 + k * HIDF))[lane];   // cols 2l, 2l+1
        u64 b0 = packff(w2.x);
        u64 b1p = packff(w2.y);
#pragma unroll
        for (int rp = 0; rp < 4; rp++) {
            u64 a = *reinterpret_cast<const u64*>(&sx[k][rbase + rp * 2]);
            ffma2(acc[rp][0], a, b0);
            ffma2(acc[rp][1], a, b1p);
        }
    }

    float2 bv = ((const float2*)b1)[lane];
#pragma unroll
    for (int rp = 0; rp < 4; rp++) {
        float2 c0 = unpackff(acc[rp][0]);
        float2 c1 = unpackff(acc[rp][1]);
        int row = row0 + rbase + rp * 2;
        float2 r0 = make_float2(fmaxf(c0.x + bv.x, 0.f), fmaxf(c1.x + bv.y, 0.f));
        float2 r1 = make_float2(fmaxf(c0.y + bv.x, 0.f), fmaxf(c1.y + bv.y, 0.f));
        ((float2*)(h + (size_t)row * HIDF))[lane]       = r0;
        ((float2*)(h + (size_t)(row + 1) * HIDF))[lane] = r1;
    }
}

// ---------------------------------------------------------------------------
// Gather SpMM v3: one warp per dst node.
// Batch-load up to 32 csr entries with ONE coalesced LDG.64 per lane,
// then shfl-broadcast (src, w) to all lanes. f-gathers have no dependency
// on in-flight loads -> deep MLP, single L2 round trip per 32 edges for csr.
__global__ __launch_bounds__(256) void k_spmm_csr(const float* __restrict__ f,
                                                  const float* __restrict__ h,
                                                  const int2* __restrict__ csr,
                                                  const int* __restrict__ rowp,
                                                  const int* __restrict__ deg,
                                                  const float* __restrict__ dis,
                                                  const float* __restrict__ alpha,
                                                  const float* __restrict__ beta,
                                                  float* __restrict__ fout) {
    int node = (blockIdx.x * blockDim.x + threadIdx.x) >> 5;
    if (node >= NN) return;
    int lane = threadIdx.x & 31;

    int beg = rowp[node];
    int n   = deg[node];

    float ax = 0.f, ay = 0.f;

    for (int c = 0; c < n; c += 32) {
        int m = n - c; if (m > 32) m = 32;
        int2 me = make_int2(0, 0);
        if (lane < m) me = __ldg(&csr[beg + c + lane]);   // coalesced batch

        int j = 0;
        for (; j + 4 <= m; j += 4) {
            int   s0 = __shfl_sync(0xffffffffu, me.x, j + 0);
            int   s1 = __shfl_sync(0xffffffffu, me.x, j + 1);
            int   s2 = __shfl_sync(0xffffffffu, me.x, j + 2);
            int   s3 = __shfl_sync(0xffffffffu, me.x, j + 3);
            float w0 = __int_as_float(__shfl_sync(0xffffffffu, me.y, j + 0));
            float w1 = __int_as_float(__shfl_sync(0xffffffffu, me.y, j + 1));
            float w2 = __int_as_float(__shfl_sync(0xffffffffu, me.y, j + 2));
            float w3 = __int_as_float(__shfl_sync(0xffffffffu, me.y, j + 3));
            float2 v0 = ((const float2*)(f + (size_t)s0 * HIDF))[lane];
            float2 v1 = ((const float2*)(f + (size_t)s1 * HIDF))[lane];
            float2 v2 = ((const float2*)(f + (size_t)s2 * HIDF))[lane];
            float2 v3 = ((const float2*)(f + (size_t)s3 * HIDF))[lane];
            ax = fmaf(w0, v0.x, ax); ay = fmaf(w0, v0.y, ay);
            ax = fmaf(w1, v1.x, ax); ay = fmaf(w1, v1.y, ay);
            ax = fmaf(w2, v2.x, ax); ay = fmaf(w2, v2.y, ay);
            ax = fmaf(w3, v3.x, ax); ay = fmaf(w3, v3.y, ay);
        }
        for (; j < m; j++) {
            int   s0 = __shfl_sync(0xffffffffu, me.x, j);
            float w0 = __int_as_float(__shfl_sync(0xffffffffu, me.y, j));
            float2 v0 = ((const float2*)(f + (size_t)s0 * HIDF))[lane];
            ax = fmaf(w0, v0.x, ax); ay = fmaf(w0, v0.y, ay);
        }
    }

    float scale = alpha[node] * dis[node];
    float b = beta[node];
    float2 hv = ((const float2*)(h + (size_t)node * HIDF))[lane];
    float2 r;
    r.x = fmaf(scale, ax, b * hv.x);
    r.y = fmaf(scale, ay, b * hv.y);
    ((float2*)(fout + (size_t)node * HIDF))[lane] = r;
}

// ---------------------------------------------------------------------------
// GEMM2 + log_softmax, one warp per row. Also re-zeros deg for next launch.
__global__ __launch_bounds__(256) void k_out(const float* __restrict__ f,
                                             const float* __restrict__ W2,
                                             const float* __restrict__ b2,
                                             float* __restrict__ out,
                                             int* __restrict__ deg) {
    int gwarp = (blockIdx.x * blockDim.x + threadIdx.x) >> 5;
    int lane  = threadIdx.x & 31;
    if (gwarp >= NN) return;

    if (lane == 0) deg[gwarp] = 0;

    float2 fr = ((const float2*)(f + (size_t)gwarp * HIDF))[lane];

    float acc0 = b2[lane];
    float acc1 = (lane < 8) ? b2[lane + 32] : -1e30f;

#pragma unroll
    for (int k = 0; k < HIDF; k++) {
        float fv = __shfl_sync(0xffffffffu, (k & 1) ? fr.y : fr.x, k >> 1);
        acc0 = fmaf(fv, W2[k * OUTF + lane], acc0);
        if (lane < 8) acc1 = fmaf(fv, W2[k * OUTF + lane + 32], acc1);
    }

    float m = fmaxf(acc0, acc1);
#pragma unroll
    for (int o = 16; o > 0; o >>= 1) m = fmaxf(m, __shfl_xor_sync(0xffffffffu, m, o));
    float s = expf(acc0 - m) + ((lane < 8) ? expf(acc1 - m) : 0.f);
#pragma unroll
    for (int o = 16; o > 0; o >>= 1) s += __shfl_xor_sync(0xffffffffu, s, o);
    float ls = m + logf(s);

    out[(size_t)gwarp * OUTF + lane] = acc0 - ls;
    if (lane < 8) out[(size_t)gwarp * OUTF + lane + 32] = acc1 - ls;
}

// ---------------------------------------------------------------------------
extern "C" void kernel_launch(void* const* d_in, const int* in_sizes, int n_in,
                              void* d_out, int out_size) {
    const float* x   = (const float*)d_in[0];
    const int*   ei  = (const int*)  d_in[1];
    const float* W1  = (const float*)d_in[2];
    const float* b1  = (const float*)d_in[3];
    const float* W2  = (const float*)d_in[4];
    const float* b2  = (const float*)d_in[5];
    float* out = (float*)d_out;

    const int E = in_sizes[1] / 2;
    const int* src = ei;
    const int* dst = ei + E;

    float *h, *f1, *f2, *dis, *alpha, *beta;
    int *deg, *part, *bsum, *rowp, *cur;
    int2* csr;
    cudaGetSymbolAddress((void**)&h,     g_h);
    cudaGetSymbolAddress((void**)&f1,    g_f1);
    cudaGetSymbolAddress((void**)&f2,    g_f2);
    cudaGetSymbolAddress((void**)&dis,   g_dis);
    cudaGetSymbolAddress((void**)&alpha, g_alpha);
    cudaGetSymbolAddress((void**)&beta,  g_beta);
    cudaGetSymbolAddress((void**)&deg,   g_deg);
    cudaGetSymbolAddress((void**)&part,  g_part);
    cudaGetSymbolAddress((void**)&bsum,  g_bsum);
    cudaGetSymbolAddress((void**)&rowp,  g_rowp);
    cudaGetSymbolAddress((void**)&cur,   g_cur);
    cudaGetSymbolAddress((void**)&csr,   g_csr);

    // one-time stream/event setup
    static cudaStream_t sB = 0;
    static cudaEvent_t evRoot = 0, evB = 0;
    static int use_fork = -1;
    if (use_fork < 0) {
        use_fork = 1;
        if (cudaStreamCreateWithFlags(&sB, cudaStreamNonBlocking) != cudaSuccess) use_fork = 0;
        if (use_fork && cudaEventCreateWithFlags(&evRoot, cudaEventDisableTiming) != cudaSuccess) use_fork = 0;
        if (use_fork && cudaEventCreateWithFlags(&evB, cudaEventDisableTiming) != cudaSuccess) use_fork = 0;
    }
    cudaStream_t sG = 0;
    if (use_fork) {
        cudaEventRecord(evRoot, 0);
        cudaStreamWaitEvent(sB, evRoot, 0);
        sG = sB;
    }

    // prep chain on stream 0; k_fill in profiled slot (4th kernel submission)
    k_degree <<<(E + 255) / 256, 256>>>(dst, deg, E);                    // submit #1
    k_scan1f <<<NB_SCAN, SCAN_B>>>(deg, part, bsum, dis, alpha, beta);   // submit #2
    k_scan23 <<<NB_SCAN, SCAN_B>>>(part, bsum, rowp, cur);               // submit #3
    k_fill   <<<(E + 255) / 256, 256>>>(src, dst, dis, cur, csr, E);     // submit #4  <- profiled
    k_gemm1  <<<NN / 32, 128, 0, sG>>>(x, W1, b1, h);                    // submit #5 (fork)

    if (use_fork) {
        cudaEventRecord(evB, sB);
        cudaStreamWaitEvent(0, evB, 0);
    }

    k_spmm_csr<<<(NN * 32 + 255) / 256, 256>>>(h,  h, csr, rowp, deg, dis, alpha, beta, f1);
    k_spmm_csr<<<(NN * 32 + 255) / 256, 256>>>(f1, h, csr, rowp, deg, dis, alpha, beta, f2);

    k_out<<<(NN * 32 + 255) / 256, 256>>>(f2, W2, b2, out, deg);
}